// round 13
// baseline (speedup 1.0000x reference)
#include <cuda_runtime.h>
#include <cuda_fp16.h>
#include <math.h>
#include <stdint.h>

#define BSZ 2
#define SEQ 2048
#define DM  2048
#define HQ  16
#define HKV 4
#define HD  128
#define MROWS (BSZ*SEQ)        // 4096
#define KVD (HKV*HD)           // 512
#define NBH (BSZ*HQ)           // 32
#define NTILE (SEQ/128)        // 16

// ---------------- persistent scratch ----------------------------------------
__device__ __half g_xh [(size_t)MROWS*DM];
__device__ __half g_qh [(size_t)MROWS*DM];
__device__ __half g_kh [(size_t)MROWS*KVD];
__device__ __half g_vh [(size_t)MROWS*KVD];
__device__ __half g_vt [(size_t)BSZ*HKV*HD*SEQ];   // [b][hk][d][s]
__device__ __half g_aoh[(size_t)MROWS*DM];
__device__ __half g_wqt[(size_t)DM*DM];            // [N][K]
__device__ __half g_wkt[(size_t)KVD*DM];
__device__ __half g_wvt[(size_t)KVD*DM];
__device__ __half g_wot[(size_t)DM*DM];
__device__ __half g_sh [(size_t)NBH*NTILE*NTILE*128*128];  // fp16 score tiles
__device__ float  g_M  [(size_t)NBH*SEQ];          // row max
__device__ float  g_Li [(size_t)NBH*SEQ];          // 1/row sum

// ---------------- helpers ---------------------------------------------------
__device__ __forceinline__ uint32_t pack2(float lo, float hi){
    __half2 h = __floats2half2_rn(lo, hi);
    return *reinterpret_cast<uint32_t*>(&h);
}
__device__ __forceinline__ uint32_t smem_u32(const void* p){
    uint32_t a;
    asm("{ .reg .u64 t; cvta.to.shared.u64 t, %1; cvt.u32.u64 %0, t; }"
        : "=r"(a) : "l"(p));
    return a;
}
__device__ __forceinline__ void cp16(uint32_t dst, const void* src){
    asm volatile("cp.async.cg.shared.global [%0], [%1], 16;"
        :: "r"(dst), "l"(src) : "memory");
}
#define CP_COMMIT() asm volatile("cp.async.commit_group;" ::: "memory")
#define CP_WAIT0()  asm volatile("cp.async.wait_group 0;" ::: "memory")
#define CP_WAIT1()  asm volatile("cp.async.wait_group 1;" ::: "memory")

__device__ __forceinline__ void ldsm_x4(uint32_t* r, uint32_t addr){
    asm volatile("ldmatrix.sync.aligned.m8n8.x4.shared.b16 {%0,%1,%2,%3}, [%4];"
        : "=r"(r[0]), "=r"(r[1]), "=r"(r[2]), "=r"(r[3]) : "r"(addr));
}
__device__ __forceinline__ void ldsm_x2(uint32_t* r, uint32_t addr){
    asm volatile("ldmatrix.sync.aligned.m8n8.x2.shared.b16 {%0,%1}, [%2];"
        : "=r"(r[0]), "=r"(r[1]) : "r"(addr));
}
__device__ __forceinline__ void mma_f16(float* d, const uint32_t* a, const uint32_t* b){
    asm volatile("mma.sync.aligned.m16n8k16.row.col.f32.f16.f16.f32 "
        "{%0,%1,%2,%3}, {%4,%5,%6,%7}, {%8,%9}, {%0,%1,%2,%3};"
        : "+f"(d[0]), "+f"(d[1]), "+f"(d[2]), "+f"(d[3])
        : "r"(a[0]), "r"(a[1]), "r"(a[2]), "r"(a[3]), "r"(b[0]), "r"(b[1]));
}

#define ACC_INIT(acc) \
    _Pragma("unroll") for (int i=0;i<4;i++) \
        _Pragma("unroll") for (int j=0;j<4;j++) \
            _Pragma("unroll") for (int v=0;v<4;v++) acc[i][j][v]=0.f;

// projection smem: 3 stages x (A 128x40 + B 256x40) halves
#define PROJ_SMEM (3 * (10240 + 20480))    // 92160 B
// scores smem: Q 4 chunks + K 3 bufs + reductions
#define SCORES_SMEM ((20480 + 15360)*2 + 1280*4)   // 76800 B

// ====== fp16 wide proj core: 128x256 block, 64x64 warp tile, 3-stage ========
template<int CF>
__device__ __forceinline__ void tc_wide(
    const __half* __restrict__ A, int lda, const __half* __restrict__ B, int ldb,
    void* Cv, int ldc, const float* __restrict__ bias, int niter,
    const float* __restrict__ cosb, const float* __restrict__ sinb, int srow)
{
    extern __shared__ __half dsm[];
    __half* Asb = dsm;                 // 3 x 5120 halves
    __half* Bsb = dsm + 3*5120;        // 3 x 10240 halves

    const int t = threadIdx.x, lane = t & 31, w = t >> 5;
    const int wm = w >> 2, wn = w & 3, gid = lane >> 2, tg = lane & 3;
    const int row = t >> 1, ch = (t & 1) * 16;

    float acc[4][8][4];
    #pragma unroll
    for (int i=0;i<4;i++)
        #pragma unroll
        for (int j=0;j<8;j++)
            #pragma unroll
            for (int v=0;v<4;v++) acc[i][j][v]=0.f;

    const __half* Ag  = A + (size_t)row * lda + ch;
    const __half* Bg  = B + (size_t)row * ldb + ch;
    const __half* Bg2 = Bg + (size_t)128 * ldb;

    const uint32_t aoff = ((wm*64 + (lane & 15)) * 40 + ((lane >> 4) << 3)) << 1;
    const uint32_t boff = ((wn*64 + (lane & 7) + ((lane >> 4) << 3)) * 40
                          + (((lane >> 3) & 1) << 3)) << 1;
    const uint32_t soff = (row*40 + ch) << 1;

    uint32_t stA0 = smem_u32(Asb) + soff,  stB0 = smem_u32(Bsb) + soff;
    uint32_t stA1 = stA0 + 10240,          stB1 = stB0 + 20480;
    uint32_t stA2 = stA1 + 10240,          stB2 = stB1 + 20480;
    uint32_t ldA0 = smem_u32(Asb) + aoff,  ldB0 = smem_u32(Bsb) + boff;
    uint32_t ldA1 = ldA0 + 10240,          ldB1 = ldB0 + 20480;
    uint32_t ldA2 = ldA1 + 10240,          ldB2 = ldB1 + 20480;

    {
        cp16(stA0, Ag);           cp16(stA0 + 16, Ag + 8);
        cp16(stB0, Bg);           cp16(stB0 + 16, Bg + 8);
        cp16(stB0 + 10240, Bg2);  cp16(stB0 + 10240 + 16, Bg2 + 8);
        CP_COMMIT();
        cp16(stA1, Ag + 32);          cp16(stA1 + 16, Ag + 40);
        cp16(stB1, Bg + 32);          cp16(stB1 + 16, Bg + 40);
        cp16(stB1 + 10240, Bg2 + 32); cp16(stB1 + 10240 + 16, Bg2 + 40);
        CP_COMMIT();
    }

    for (int it = 0; it < niter; ++it) {
        if (it + 1 < niter) { CP_WAIT1(); } else { CP_WAIT0(); }
        __syncthreads();
        if (it + 2 < niter) {
            const __half* a  = Ag  + (size_t)(it + 2) * 32;
            const __half* b  = Bg  + (size_t)(it + 2) * 32;
            const __half* b2 = Bg2 + (size_t)(it + 2) * 32;
            cp16(stA2, a);           cp16(stA2 + 16, a + 8);
            cp16(stB2, b);           cp16(stB2 + 16, b + 8);
            cp16(stB2 + 10240, b2);  cp16(stB2 + 10240 + 16, b2 + 8);
            CP_COMMIT();
        }
        #pragma unroll
        for (int c = 0; c < 2; ++c) {
            uint32_t af[4][4], bf[8][2];
            #pragma unroll
            for (int mt = 0; mt < 4; ++mt)
                ldsm_x4(af[mt], ldA0 + mt * 1280 + c * 32);
            #pragma unroll
            for (int ng = 0; ng < 4; ++ng) {
                uint32_t qf[4];
                ldsm_x4(qf, ldB0 + ng * 1280 + c * 32);
                bf[2*ng][0]   = qf[0]; bf[2*ng][1]   = qf[1];
                bf[2*ng+1][0] = qf[2]; bf[2*ng+1][1] = qf[3];
            }
            #pragma unroll
            for (int mt = 0; mt < 4; ++mt)
                #pragma unroll
                for (int nt = 0; nt < 8; ++nt)
                    mma_f16(acc[mt][nt], af[mt], bf[nt]);
        }
        uint32_t tmp;
        tmp = stA0; stA0 = stA1; stA1 = stA2; stA2 = tmp;
        tmp = stB0; stB0 = stB1; stB1 = stB2; stB2 = tmp;
        tmp = ldA0; ldA0 = ldA1; ldA1 = ldA2; ldA2 = tmp;
        tmp = ldB0; ldB0 = ldB1; ldB1 = ldB2; ldB2 = tmp;
    }

    #pragma unroll
    for (int mt = 0; mt < 4; ++mt) {
        const int r0 = wm*64 + mt*16 + gid;
        #pragma unroll
        for (int nt = 0; nt < 8; ++nt) {
            const int cn = wn*64 + nt*8 + 2*tg;
            float b0 = 0.f, b1 = 0.f;
            if (bias) { b0 = bias[cn]; b1 = bias[cn+1]; }
            float v00 = acc[mt][nt][0] + b0;
            float v01 = acc[mt][nt][1] + b1;
            float v10 = acc[mt][nt][2] + b0;
            float v11 = acc[mt][nt][3] + b1;
            if (cosb) {
                const int p = (cn & 127) >> 1;
                const float c0 = cosb[(srow + r0) * 64 + p];
                const float s0 = sinb[(srow + r0) * 64 + p];
                const float c1 = cosb[(srow + r0 + 8) * 64 + p];
                const float s1 = sinb[(srow + r0 + 8) * 64 + p];
                float t0 = v00*c0 - v01*s0, t1 = v00*s0 + v01*c0;
                v00 = t0; v01 = t1;
                t0 = v10*c1 - v11*s1; t1 = v10*s1 + v11*c1;
                v10 = t0; v11 = t1;
            }
            if (CF == 1) {
                float* C = (float*)Cv;
                *(float2*)(C + (size_t)r0*ldc + cn)     = make_float2(v00, v01);
                *(float2*)(C + (size_t)(r0+8)*ldc + cn) = make_float2(v10, v11);
            } else {
                __half* C = (__half*)Cv;
                *(uint32_t*)(C + (size_t)r0*ldc + cn)     = pack2(v00, v01);
                *(uint32_t*)(C + (size_t)(r0+8)*ldc + cn) = pack2(v10, v11);
            }
        }
    }
}

// ---------------- GEMM wrappers ---------------------------------------------
__global__ __launch_bounds__(256) void k_qkv(
    const __half* __restrict__ xh,
    const __half* __restrict__ wqt, const __half* __restrict__ wkt,
    const __half* __restrict__ wvt,
    const float* __restrict__ bq, const float* __restrict__ bk,
    const float* __restrict__ bv,
    __half* __restrict__ qh, __half* __restrict__ kh, __half* __restrict__ vh,
    const float* __restrict__ cosb, const float* __restrict__ sinb)
{
    const int bx = blockIdx.x, by = blockIdx.y;
    const __half* A = xh + (size_t)by * 128 * DM;
    const int srow = (by & 15) * 128;
    if (bx < 8) {
        tc_wide<0>(A, DM, wqt + (size_t)bx*256*DM, DM,
                   qh + (size_t)by*128*DM + bx*256, DM,
                   bq + bx*256, DM/32, cosb, sinb, srow);
    } else if (bx < 10) {
        const int c = bx - 8;
        tc_wide<0>(A, DM, wkt + (size_t)c*256*DM, DM,
                   kh + (size_t)by*128*KVD + c*256, KVD,
                   bk + c*256, DM/32, cosb, sinb, srow);
    } else {
        const int c = bx - 10;
        tc_wide<0>(A, DM, wvt + (size_t)c*256*DM, DM,
                   vh + (size_t)by*128*KVD + c*256, KVD,
                   bv + c*256, DM/32, (const float*)0, (const float*)0, 0);
    }
}

__global__ __launch_bounds__(256) void k_proj_o(
    const __half* __restrict__ X, const __half* __restrict__ Wt,
    float* __restrict__ C)
{
    tc_wide<1>(X + (size_t)blockIdx.y*128*DM, DM,
               Wt + (size_t)blockIdx.x*256*DM, DM,
               C + (size_t)blockIdx.y*128*DM + blockIdx.x*256, DM,
               (const float*)0, DM/32, (const float*)0, (const float*)0, 0);
}

// ======== persistent scores: CTA per (bh, by), 3-stage K pipeline ===========
__global__ __launch_bounds__(256) void k_scores_p(
    const __half* __restrict__ q, const __half* __restrict__ k,
    __half* __restrict__ sh, float* __restrict__ Mv, float* __restrict__ Li,
    float scale)
{
    const int by = NTILE - 1 - blockIdx.x;       // big rows first
    const int bh = blockIdx.y;
    const int b = bh >> 4, h = bh & 15, hk = h >> 2;

    extern __shared__ __half dsm[];
    __half* Qs = dsm;                  // 4 chunks x 128x40 = 20480 halves
    __half* Ks = dsm + 20480;          // 3 bufs   x 128x40 = 15360 halves
    float* sm_m = (float*)(dsm + 20480 + 15360);   // [4][128]
    float* sm_l = sm_m + 512;              // [4][128]
    float* runM = sm_l + 512;              // [128]
    float* runL = runM + 128;              // [128]

    const int t = threadIdx.x, lane = t & 31, w = t >> 5;
    const int wm = w >> 2, wn = w & 3, gid = lane >> 2, tg = lane & 3;
    const int row = t >> 1, ch = (t & 1) * 16;

    if (t < 128) { runM[t] = -1e30f; runL[t] = 0.f; }

    const __half* Qg = q + ((size_t)b*SEQ + by*128 + row) * DM  + h*HD  + ch;
    const __half* Kb = k + ((size_t)b*SEQ + row) * KVD + hk*HD + ch;

    const uint32_t qst = smem_u32(Qs) + ((row*40 + ch) << 1);
    const uint32_t kbase_st = smem_u32(Ks) + ((row*40 + ch) << 1);
    const uint32_t qld = smem_u32(Qs) +
        (((wm*64 + (lane & 15)) * 40 + ((lane >> 4) << 3)) << 1);
    const uint32_t kbase_ld = smem_u32(Ks) +
        (((wn*32 + (lane & 7)) * 40 + (((lane >> 3) & 1) << 3)) << 1);

    // rotating 3-stage K addresses
    uint32_t kst0 = kbase_st, kst1 = kbase_st + 10240, kst2 = kbase_st + 20480;
    uint32_t kld0 = kbase_ld, kld1 = kbase_ld + 10240, kld2 = kbase_ld + 20480;

    auto ksrc = [&](int g) -> const __half* {
        return Kb + (size_t)((g >> 2) * 128) * KVD + (g & 3) * 32;
    };

    // prologue: Q (own group), then K0, K1
    #pragma unroll
    for (int c4 = 0; c4 < 4; ++c4) {
        cp16(qst + c4*10240, Qg + c4*32);
        cp16(qst + c4*10240 + 16, Qg + c4*32 + 8);
    }
    CP_COMMIT();
    { const __half* s0 = ksrc(0); cp16(kst0, s0); cp16(kst0 + 16, s0 + 8); }
    CP_COMMIT();
    { const __half* s1 = ksrc(1); cp16(kst1, s1); cp16(kst1 + 16, s1 + 8); }
    CP_COMMIT();

    float acc[4][4][4];
    const int G = 4 * (by + 1);          // G >= 4
    for (int g = 0; g < G; ++g) {
        const int bx = g >> 2, c4 = g & 3;
        if (c4 == 0) { ACC_INIT(acc) }
        if (g + 1 < G) { CP_WAIT1(); } else { CP_WAIT0(); }
        __syncthreads();
        if (g + 2 < G) {
            const __half* s2 = ksrc(g + 2);
            cp16(kst2, s2); cp16(kst2 + 16, s2 + 8);
            CP_COMMIT();
        }
        #pragma unroll
        for (int c = 0; c < 2; ++c) {
            uint32_t af[4][4], bf[4][2];
            #pragma unroll
            for (int mt = 0; mt < 4; ++mt)
                ldsm_x4(af[mt], qld + c4*10240 + mt * 1280 + c * 32);
            #pragma unroll
            for (int nt = 0; nt < 4; ++nt)
                ldsm_x2(bf[nt], kld0 + nt * 640 + c * 32);
            #pragma unroll
            for (int mt = 0; mt < 4; ++mt)
                #pragma unroll
                for (int nt = 0; nt < 4; ++nt)
                    mma_f16(acc[mt][nt], af[mt], bf[nt]);
        }
        // rotate K stages
        { uint32_t tmp = kst0; kst0 = kst1; kst1 = kst2; kst2 = tmp;
          tmp = kld0; kld0 = kld1; kld1 = kld2; kld2 = tmp; }

        if (c4 == 3) {
            // epilogue for tile bx: store S fp16, update running max/sum
            const bool diag = (bx == by);
            __half* tile = sh + (((size_t)bh*NTILE + by)*NTILE + bx) * (128*128);
            #pragma unroll
            for (int mt = 0; mt < 4; ++mt) {
                #pragma unroll
                for (int hv = 0; hv < 2; ++hv) {
                    const int r = wm*64 + mt*16 + gid + hv*8;
                    float vals[8];
                    #pragma unroll
                    for (int nt = 0; nt < 4; ++nt) {
                        vals[nt*2]   = acc[mt][nt][hv*2]   * scale;
                        vals[nt*2+1] = acc[mt][nt][hv*2+1] * scale;
                        const int cn = wn*32 + nt*8 + 2*tg;
                        *(uint32_t*)(tile + (size_t)r*128 + cn) =
                            pack2(vals[nt*2], vals[nt*2+1]);
                    }
                    if (diag) {
                        #pragma unroll
                        for (int nt = 0; nt < 4; ++nt) {
                            const int cn = wn*32 + nt*8 + 2*tg;
                            if (cn     > r) vals[nt*2]   = -1e30f;
                            if (cn + 1 > r) vals[nt*2+1] = -1e30f;
                        }
                    }
                    float m = -1e30f;
                    #pragma unroll
                    for (int i = 0; i < 8; ++i) m = fmaxf(m, vals[i]);
                    m = fmaxf(m, __shfl_xor_sync(0xFFFFFFFFu, m, 1));
                    m = fmaxf(m, __shfl_xor_sync(0xFFFFFFFFu, m, 2));
                    float l = 0.f;
                    #pragma unroll
                    for (int i = 0; i < 8; ++i)
                        if (vals[i] > -1e29f) l += __expf(vals[i] - m);
                    l += __shfl_xor_sync(0xFFFFFFFFu, l, 1);
                    l += __shfl_xor_sync(0xFFFFFFFFu, l, 2);
                    if (tg == 0) { sm_m[wn*128 + r] = m; sm_l[wn*128 + r] = l; }
                }
            }
            __syncthreads();
            if (t < 128) {
                float Mt = -1e30f;
                #pragma unroll
                for (int w2 = 0; w2 < 4; ++w2)
                    Mt = fmaxf(Mt, sm_m[w2*128 + t]);
                float Lt = 0.f;
                #pragma unroll
                for (int w2 = 0; w2 < 4; ++w2)
                    if (sm_m[w2*128 + t] > -1e29f)
                        Lt += sm_l[w2*128 + t] * __expf(sm_m[w2*128 + t] - Mt);
                const float Mo = runM[t], Lo = runL[t];
                const float Mn = fmaxf(Mo, Mt);
                float Ln = 0.f;
                if (Mo > -1e29f) Ln += Lo * __expf(Mo - Mn);
                if (Mt > -1e29f) Ln += Lt * __expf(Mt - Mn);
                runM[t] = Mn; runL[t] = Ln;
            }
            __syncthreads();
        }
    }

    if (t < 128) {
        Mv[(size_t)bh*SEQ + by*128 + t] = runM[t];
        Li[(size_t)bh*SEQ + by*128 + t] = 1.0f / runL[t];
    }
}

// ======== fused normalize + P write + P@V + upper zero-fill =================
__global__ __launch_bounds__(256) void k_pv(
    const __half* __restrict__ sh, const float* __restrict__ Mv,
    const float* __restrict__ Li, const __half* __restrict__ vt,
    float* __restrict__ attn, __half* __restrict__ ao)
{
    const int by = NTILE - 1 - blockIdx.x;       // big tiles first
    const int bh = blockIdx.y;
    const int b = bh >> 4, h = bh & 15, hk = h >> 2;
    const int i0 = by * 128;

    __shared__ __half As[128*40];
    __shared__ __half Bs[128*40];
    const int t = threadIdx.x, lane = t & 31, w = t >> 5;
    const int wm = w >> 2, wn = w & 3, gid = lane >> 2, tg = lane & 3;
    const int row = t >> 1, ch = (t & 1) * 16;

    float acc[4][4][4];
    ACC_INIT(acc)

    const float Mrow = Mv[(size_t)bh*SEQ + i0 + row];
    const float invL = Li[(size_t)bh*SEQ + i0 + row];
    const __half* shb = sh + ((size_t)bh*NTILE + by)*NTILE*(128*128);
    const __half* vtp = vt + (size_t)(b*HKV + hk)*HD*SEQ + (size_t)row*SEQ + ch;
    float* arow = attn + ((size_t)bh*SEQ + i0 + row)*SEQ;

    const uint32_t aAddr = smem_u32(As) +
        (((wm*64 + (lane & 15)) * 40 + ((lane >> 4) << 3)) << 1);
    const uint32_t bAddr = smem_u32(Bs) +
        (((wn*32 + (lane & 7)) * 40 + (((lane >> 3) & 1) << 3)) << 1);

    const int njc = (by + 1) * 4;

    auto sptr = [&](int jc) -> const __half* {
        const int tj = jc >> 2, jin = (jc & 3) * 32;
        return shb + (size_t)tj*(128*128) + (size_t)row*128 + jin + ch;
    };

    uint4 sv0, sv1, vv0, vv1;
    {
        const __half* sp = sptr(0);
        sv0 = *(const uint4*)sp;  sv1 = *(const uint4*)(sp + 8);
        vv0 = *(const uint4*)vtp; vv1 = *(const uint4*)(vtp + 8);
    }

    for (int jc = 0; jc < njc; ++jc) {
        const int tj = jc >> 2, jin = (jc & 3) * 32;

        float p[16];
        {
            const __half2* h2 = (const __half2*)&sv0;
            #pragma unroll
            for (int g = 0; g < 4; ++g) {
                float2 f = __half22float2(h2[g]);
                p[g*2]   = __expf(f.x - Mrow) * invL;
                p[g*2+1] = __expf(f.y - Mrow) * invL;
            }
            const __half2* h3 = (const __half2*)&sv1;
            #pragma unroll
            for (int g = 0; g < 4; ++g) {
                float2 f = __half22float2(h3[g]);
                p[8+g*2]   = __expf(f.x - Mrow) * invL;
                p[8+g*2+1] = __expf(f.y - Mrow) * invL;
            }
        }
        if (tj == by) {
            #pragma unroll
            for (int kk = 0; kk < 16; ++kk)
                if (jin + ch + kk > row) p[kk] = 0.f;
        }
        float* ap = arow + tj*128 + jin + ch;
        *(float4*)(ap)      = make_float4(p[0],  p[1],  p[2],  p[3]);
        *(float4*)(ap + 4)  = make_float4(p[4],  p[5],  p[6],  p[7]);
        *(float4*)(ap + 8)  = make_float4(p[8],  p[9],  p[10], p[11]);
        *(float4*)(ap + 12) = make_float4(p[12], p[13], p[14], p[15]);

        uint4* aw = (uint4*)&As[row*40 + ch];
        aw[0] = make_uint4(pack2(p[0],p[1]),  pack2(p[2],p[3]),
                           pack2(p[4],p[5]),  pack2(p[6],p[7]));
        aw[1] = make_uint4(pack2(p[8],p[9]),  pack2(p[10],p[11]),
                           pack2(p[12],p[13]),pack2(p[14],p[15]));
        uint4* bw = (uint4*)&Bs[row*40 + ch];
        bw[0] = vv0;
        bw[1] = vv1;

        if (jc + 1 < njc) {
            const __half* sp = sptr(jc + 1);
            sv0 = *(const uint4*)sp;  sv1 = *(const uint4*)(sp + 8);
            const __half* vp = vtp + (jc + 1)*32;
            vv0 = *(const uint4*)vp;  vv1 = *(const uint4*)(vp + 8);
        }
        __syncthreads();

        #pragma unroll
        for (int c = 0; c < 2; ++c) {
            uint32_t af[4][4], bf[4][2];
            #pragma unroll
            for (int mt = 0; mt < 4; ++mt)
                ldsm_x4(af[mt], aAddr + mt * 1280 + c * 32);
            #pragma unroll
            for (int nt = 0; nt < 4; ++nt)
                ldsm_x2(bf[nt], bAddr + nt * 640 + c * 32);
            #pragma unroll
            for (int mt = 0; mt < 4; ++mt)
                #pragma unroll
                for (int nt = 0; nt < 4; ++nt)
                    mma_f16(acc[mt][nt], af[mt], bf[nt]);
        }
        __syncthreads();
    }

    #pragma unroll
    for (int mt = 0; mt < 4; ++mt) {
        const int r0 = wm*64 + mt*16 + gid;
        #pragma unroll
        for (int nt = 0; nt < 4; ++nt) {
            const int cn = wn*32 + nt*8 + 2*tg;
            __half* C = ao + ((size_t)b*SEQ + i0)*DM + h*HD;
            *(uint32_t*)(C + (size_t)r0*DM + cn) =
                pack2(acc[mt][nt][0], acc[mt][nt][1]);
            *(uint32_t*)(C + (size_t)(r0+8)*DM + cn) =
                pack2(acc[mt][nt][2], acc[mt][nt][3]);
        }
    }

    // zero-fill the strictly-upper attn tiles of these rows (balances work)
    {
        const int ofs = (t & 1) * 64;
        const float4 z = make_float4(0.f, 0.f, 0.f, 0.f);
        for (int tj = by + 1; tj < NTILE; ++tj) {
            float* ap = arow + tj*128 + ofs;
            #pragma unroll
            for (int i = 0; i < 16; ++i)
                *(float4*)(ap + i*4) = z;
        }
    }
}

// ---------------- converts / transposes -------------------------------------
__global__ void k_cvt_x(const float* __restrict__ x, __half* __restrict__ xh, int n4)
{
    int i = blockIdx.x * blockDim.x + threadIdx.x;
    if (i >= n4) return;
    float4 v = ((const float4*)x)[i];
    ((uint2*)xh)[i] = make_uint2(pack2(v.x, v.y), pack2(v.z, v.w));
}

__global__ __launch_bounds__(256) void k_cvt_w(
    const float* __restrict__ src, __half* __restrict__ dst, int N, int K)
{
    __shared__ float tile[32][33];
    const int tx = threadIdx.x & 31, ty = threadIdx.x >> 5;
    const int r0 = blockIdx.y * 32, c0 = blockIdx.x * 32;
    #pragma unroll
    for (int i = 0; i < 32; i += 8)
        tile[ty + i][tx] = src[(size_t)(r0 + ty + i) * N + c0 + tx];
    __syncthreads();
    #pragma unroll
    for (int i = 0; i < 32; i += 8)
        dst[(size_t)(c0 + ty + i) * K + r0 + tx] = __float2half(tile[tx][ty + i]);
}

__global__ __launch_bounds__(256) void k_transpose_v(
    const __half* __restrict__ v, __half* __restrict__ vt)
{
    __shared__ __half tile[32][33];
    const int z = blockIdx.z, b = z >> 2, hk = z & 3;
    const int tx = threadIdx.x & 31, ty = threadIdx.x >> 5;
    const int r0 = blockIdx.y * 32, c0 = blockIdx.x * 32;
    #pragma unroll
    for (int i = 0; i < 32; i += 8)
        tile[ty + i][tx] = v[((size_t)b*SEQ + r0 + ty + i) * KVD + hk*HD + c0 + tx];
    __syncthreads();
    #pragma unroll
    for (int i = 0; i < 32; i += 8)
        vt[((size_t)(b*HKV + hk)*HD + c0 + ty + i) * SEQ + r0 + tx] = tile[tx][ty + i];
}

// ---------------- launch ------------------------------------------------------
extern "C" void kernel_launch(void* const* d_in, const int* in_sizes, int n_in,
                              void* d_out, int out_size)
{
    const float* x  = (const float*)d_in[0];
    const float* fc = (const float*)d_in[1];
    const float* fs = (const float*)d_in[2];
    const float* wq = (const float*)d_in[3];
    const float* bq = (const float*)d_in[4];
    const float* wk = (const float*)d_in[5];
    const float* bk = (const float*)d_in[6];
    const float* wv = (const float*)d_in[7];
    const float* bv = (const float*)d_in[8];
    const float* wo = (const float*)d_in[9];

    float* outp = (float*)d_out;
    float* attn = outp + (size_t)BSZ * SEQ * DM;

    __half *xh, *qh, *kh, *vh, *vt, *aoh, *wqt, *wkt, *wvt, *wot, *sh;
    float *Mv, *Li;
    cudaGetSymbolAddress((void**)&xh,  g_xh);
    cudaGetSymbolAddress((void**)&qh,  g_qh);
    cudaGetSymbolAddress((void**)&kh,  g_kh);
    cudaGetSymbolAddress((void**)&vh,  g_vh);
    cudaGetSymbolAddress((void**)&vt,  g_vt);
    cudaGetSymbolAddress((void**)&aoh, g_aoh);
    cudaGetSymbolAddress((void**)&wqt, g_wqt);
    cudaGetSymbolAddress((void**)&wkt, g_wkt);
    cudaGetSymbolAddress((void**)&wvt, g_wvt);
    cudaGetSymbolAddress((void**)&wot, g_wot);
    cudaGetSymbolAddress((void**)&sh,  g_sh);
    cudaGetSymbolAddress((void**)&Mv,  g_M);
    cudaGetSymbolAddress((void**)&Li,  g_Li);

    cudaFuncSetAttribute(k_qkv,     cudaFuncAttributeMaxDynamicSharedMemorySize, PROJ_SMEM);
    cudaFuncSetAttribute(k_proj_o,  cudaFuncAttributeMaxDynamicSharedMemorySize, PROJ_SMEM);
    cudaFuncSetAttribute(k_scores_p,cudaFuncAttributeMaxDynamicSharedMemorySize, SCORES_SMEM);

    const float scale = 1.0f / sqrtf((float)DM);

    // conversions (launches 1-5)
    k_cvt_x<<<(MROWS*DM/4 + 255)/256, 256>>>(x, xh, MROWS*DM/4);
    k_cvt_w<<<dim3(DM/32,  DM/32), 256>>>(wq, wqt, DM,  DM);
    k_cvt_w<<<dim3(KVD/32, DM/32), 256>>>(wk, wkt, KVD, DM);
    k_cvt_w<<<dim3(KVD/32, DM/32), 256>>>(wv, wvt, KVD, DM);
    k_cvt_w<<<dim3(DM/32,  DM/32), 256>>>(wo, wot, DM,  DM);

    // fused QKV projection + RoPE (wide tiles)
    k_qkv<<<dim3(12, MROWS/128), 256, PROJ_SMEM>>>(xh, wqt, wkt, wvt, bq, bk, bv,
                                                   qh, kh, vh, fc, fs);

    k_transpose_v<<<dim3(HD/32, SEQ/32, BSZ*HKV), 256>>>(vh, vt);

    // persistent scores (online softmax stats, 3-stage K pipeline)
    k_scores_p<<<dim3(NTILE, NBH), 256, SCORES_SMEM>>>(qh, kh, sh, Mv, Li, scale);

    // normalize + P + P@V + upper zero-fill
    k_pv<<<dim3(NTILE, NBH), 256>>>(sh, Mv, Li, vt, attn, aoh);

    k_proj_o<<<dim3(DM/256, MROWS/128), 256, PROJ_SMEM>>>(aoh, wot, outp);
}

// round 14
// speedup vs baseline: 1.0704x; 1.0704x over previous
#include <cuda_runtime.h>
#include <cuda_fp16.h>
#include <math.h>
#include <stdint.h>

#define BSZ 2
#define SEQ 2048
#define DM  2048
#define HQ  16
#define HKV 4
#define HD  128
#define MROWS (BSZ*SEQ)        // 4096
#define KVD (HKV*HD)           // 512
#define NBH (BSZ*HQ)           // 32
#define NTILE (SEQ/128)        // 16

// ---------------- persistent scratch ----------------------------------------
__device__ __half g_xh [(size_t)MROWS*DM];
__device__ __half g_qh [(size_t)MROWS*DM];
__device__ __half g_kh [(size_t)MROWS*KVD];
__device__ __half g_vh [(size_t)MROWS*KVD];
__device__ __half g_vt [(size_t)BSZ*HKV*HD*SEQ];   // [b][hk][d][s]
__device__ __half g_aoh[(size_t)MROWS*DM];
__device__ __half g_wqt[(size_t)DM*DM];            // [N][K]
__device__ __half g_wkt[(size_t)KVD*DM];
__device__ __half g_wvt[(size_t)KVD*DM];
__device__ __half g_wot[(size_t)DM*DM];
__device__ __half g_sh [(size_t)NBH*NTILE*NTILE*128*128];  // fp16 score tiles
__device__ float  g_pm [(size_t)NBH*SEQ*NTILE];    // per-tile row max
__device__ float  g_pl [(size_t)NBH*SEQ*NTILE];    // per-tile row expsum

// ---------------- helpers ---------------------------------------------------
__device__ __forceinline__ uint32_t pack2(float lo, float hi){
    __half2 h = __floats2half2_rn(lo, hi);
    return *reinterpret_cast<uint32_t*>(&h);
}
__device__ __forceinline__ uint32_t smem_u32(const void* p){
    uint32_t a;
    asm("{ .reg .u64 t; cvta.to.shared.u64 t, %1; cvt.u32.u64 %0, t; }"
        : "=r"(a) : "l"(p));
    return a;
}
__device__ __forceinline__ void cp16(uint32_t dst, const void* src){
    asm volatile("cp.async.cg.shared.global [%0], [%1], 16;"
        :: "r"(dst), "l"(src) : "memory");
}
#define CP_COMMIT() asm volatile("cp.async.commit_group;" ::: "memory")
#define CP_WAIT0()  asm volatile("cp.async.wait_group 0;" ::: "memory")
#define CP_WAIT1()  asm volatile("cp.async.wait_group 1;" ::: "memory")

__device__ __forceinline__ void ldsm_x4(uint32_t* r, uint32_t addr){
    asm volatile("ldmatrix.sync.aligned.m8n8.x4.shared.b16 {%0,%1,%2,%3}, [%4];"
        : "=r"(r[0]), "=r"(r[1]), "=r"(r[2]), "=r"(r[3]) : "r"(addr));
}
__device__ __forceinline__ void ldsm_x2(uint32_t* r, uint32_t addr){
    asm volatile("ldmatrix.sync.aligned.m8n8.x2.shared.b16 {%0,%1}, [%2];"
        : "=r"(r[0]), "=r"(r[1]) : "r"(addr));
}
__device__ __forceinline__ void mma_f16(float* d, const uint32_t* a, const uint32_t* b){
    asm volatile("mma.sync.aligned.m16n8k16.row.col.f32.f16.f16.f32 "
        "{%0,%1,%2,%3}, {%4,%5,%6,%7}, {%8,%9}, {%0,%1,%2,%3};"
        : "+f"(d[0]), "+f"(d[1]), "+f"(d[2]), "+f"(d[3])
        : "r"(a[0]), "r"(a[1]), "r"(a[2]), "r"(a[3]), "r"(b[0]), "r"(b[1]));
}

#define ACC_INIT(acc) \
    _Pragma("unroll") for (int i=0;i<4;i++) \
        _Pragma("unroll") for (int j=0;j<4;j++) \
            _Pragma("unroll") for (int v=0;v<4;v++) acc[i][j][v]=0.f;

// projection smem: 3 stages x (A 128x40 + B 256x40) halves
#define PROJ_SMEM (3 * (10240 + 20480))    // 92160 B

// ====== fp16 wide proj core: 128x256 block, 64x64 warp tile, 3-stage ========
template<int CF>
__device__ __forceinline__ void tc_wide(
    const __half* __restrict__ A, int lda, const __half* __restrict__ B, int ldb,
    void* Cv, int ldc, const float* __restrict__ bias, int niter,
    const float* __restrict__ cosb, const float* __restrict__ sinb, int srow)
{
    extern __shared__ __half dsm[];
    __half* Asb = dsm;                 // 3 x 5120 halves
    __half* Bsb = dsm + 3*5120;        // 3 x 10240 halves

    const int t = threadIdx.x, lane = t & 31, w = t >> 5;
    const int wm = w >> 2, wn = w & 3, gid = lane >> 2, tg = lane & 3;
    const int row = t >> 1, ch = (t & 1) * 16;

    float acc[4][8][4];
    #pragma unroll
    for (int i=0;i<4;i++)
        #pragma unroll
        for (int j=0;j<8;j++)
            #pragma unroll
            for (int v=0;v<4;v++) acc[i][j][v]=0.f;

    const __half* Ag  = A + (size_t)row * lda + ch;
    const __half* Bg  = B + (size_t)row * ldb + ch;
    const __half* Bg2 = Bg + (size_t)128 * ldb;

    const uint32_t aoff = ((wm*64 + (lane & 15)) * 40 + ((lane >> 4) << 3)) << 1;
    const uint32_t boff = ((wn*64 + (lane & 7) + ((lane >> 4) << 3)) * 40
                          + (((lane >> 3) & 1) << 3)) << 1;
    const uint32_t soff = (row*40 + ch) << 1;

    uint32_t stA0 = smem_u32(Asb) + soff,  stB0 = smem_u32(Bsb) + soff;
    uint32_t stA1 = stA0 + 10240,          stB1 = stB0 + 20480;
    uint32_t stA2 = stA1 + 10240,          stB2 = stB1 + 20480;
    uint32_t ldA0 = smem_u32(Asb) + aoff,  ldB0 = smem_u32(Bsb) + boff;
    uint32_t ldA1 = ldA0 + 10240,          ldB1 = ldB0 + 20480;
    uint32_t ldA2 = ldA1 + 10240,          ldB2 = ldB1 + 20480;

    {
        cp16(stA0, Ag);           cp16(stA0 + 16, Ag + 8);
        cp16(stB0, Bg);           cp16(stB0 + 16, Bg + 8);
        cp16(stB0 + 10240, Bg2);  cp16(stB0 + 10240 + 16, Bg2 + 8);
        CP_COMMIT();
        cp16(stA1, Ag + 32);          cp16(stA1 + 16, Ag + 40);
        cp16(stB1, Bg + 32);          cp16(stB1 + 16, Bg + 40);
        cp16(stB1 + 10240, Bg2 + 32); cp16(stB1 + 10240 + 16, Bg2 + 40);
        CP_COMMIT();
    }

    for (int it = 0; it < niter; ++it) {
        if (it + 1 < niter) { CP_WAIT1(); } else { CP_WAIT0(); }
        __syncthreads();
        if (it + 2 < niter) {
            const __half* a  = Ag  + (size_t)(it + 2) * 32;
            const __half* b  = Bg  + (size_t)(it + 2) * 32;
            const __half* b2 = Bg2 + (size_t)(it + 2) * 32;
            cp16(stA2, a);           cp16(stA2 + 16, a + 8);
            cp16(stB2, b);           cp16(stB2 + 16, b + 8);
            cp16(stB2 + 10240, b2);  cp16(stB2 + 10240 + 16, b2 + 8);
            CP_COMMIT();
        }
        #pragma unroll
        for (int c = 0; c < 2; ++c) {
            uint32_t af[4][4], bf[8][2];
            #pragma unroll
            for (int mt = 0; mt < 4; ++mt)
                ldsm_x4(af[mt], ldA0 + mt * 1280 + c * 32);
            #pragma unroll
            for (int ng = 0; ng < 4; ++ng) {
                uint32_t qf[4];
                ldsm_x4(qf, ldB0 + ng * 1280 + c * 32);
                bf[2*ng][0]   = qf[0]; bf[2*ng][1]   = qf[1];
                bf[2*ng+1][0] = qf[2]; bf[2*ng+1][1] = qf[3];
            }
            #pragma unroll
            for (int mt = 0; mt < 4; ++mt)
                #pragma unroll
                for (int nt = 0; nt < 8; ++nt)
                    mma_f16(acc[mt][nt], af[mt], bf[nt]);
        }
        uint32_t tmp;
        tmp = stA0; stA0 = stA1; stA1 = stA2; stA2 = tmp;
        tmp = stB0; stB0 = stB1; stB1 = stB2; stB2 = tmp;
        tmp = ldA0; ldA0 = ldA1; ldA1 = ldA2; ldA2 = tmp;
        tmp = ldB0; ldB0 = ldB1; ldB1 = ldB2; ldB2 = tmp;
    }

    #pragma unroll
    for (int mt = 0; mt < 4; ++mt) {
        const int r0 = wm*64 + mt*16 + gid;
        #pragma unroll
        for (int nt = 0; nt < 8; ++nt) {
            const int cn = wn*64 + nt*8 + 2*tg;
            float b0 = 0.f, b1 = 0.f;
            if (bias) { b0 = bias[cn]; b1 = bias[cn+1]; }
            float v00 = acc[mt][nt][0] + b0;
            float v01 = acc[mt][nt][1] + b1;
            float v10 = acc[mt][nt][2] + b0;
            float v11 = acc[mt][nt][3] + b1;
            if (cosb) {
                const int p = (cn & 127) >> 1;
                const float c0 = cosb[(srow + r0) * 64 + p];
                const float s0 = sinb[(srow + r0) * 64 + p];
                const float c1 = cosb[(srow + r0 + 8) * 64 + p];
                const float s1 = sinb[(srow + r0 + 8) * 64 + p];
                float t0 = v00*c0 - v01*s0, t1 = v00*s0 + v01*c0;
                v00 = t0; v01 = t1;
                t0 = v10*c1 - v11*s1; t1 = v10*s1 + v11*c1;
                v10 = t0; v11 = t1;
            }
            if (CF == 1) {
                float* C = (float*)Cv;
                *(float2*)(C + (size_t)r0*ldc + cn)     = make_float2(v00, v01);
                *(float2*)(C + (size_t)(r0+8)*ldc + cn) = make_float2(v10, v11);
            } else {
                __half* C = (__half*)Cv;
                *(uint32_t*)(C + (size_t)r0*ldc + cn)     = pack2(v00, v01);
                *(uint32_t*)(C + (size_t)(r0+8)*ldc + cn) = pack2(v10, v11);
            }
        }
    }
}

// ---------------- GEMM wrappers ---------------------------------------------
// fused QKV projection + RoPE: grid (12, 32). bx 0-7: Q; 8-9: K; 10-11: V
__global__ __launch_bounds__(256) void k_qkv(
    const __half* __restrict__ xh,
    const __half* __restrict__ wqt, const __half* __restrict__ wkt,
    const __half* __restrict__ wvt,
    const float* __restrict__ bq, const float* __restrict__ bk,
    const float* __restrict__ bv,
    __half* __restrict__ qh, __half* __restrict__ kh, __half* __restrict__ vh,
    const float* __restrict__ cosb, const float* __restrict__ sinb)
{
    const int bx = blockIdx.x, by = blockIdx.y;
    const __half* A = xh + (size_t)by * 128 * DM;
    const int srow = (by & 15) * 128;
    if (bx < 8) {
        tc_wide<0>(A, DM, wqt + (size_t)bx*256*DM, DM,
                   qh + (size_t)by*128*DM + bx*256, DM,
                   bq + bx*256, DM/32, cosb, sinb, srow);
    } else if (bx < 10) {
        const int c = bx - 8;
        tc_wide<0>(A, DM, wkt + (size_t)c*256*DM, DM,
                   kh + (size_t)by*128*KVD + c*256, KVD,
                   bk + c*256, DM/32, cosb, sinb, srow);
    } else {
        const int c = bx - 10;
        tc_wide<0>(A, DM, wvt + (size_t)c*256*DM, DM,
                   vh + (size_t)by*128*KVD + c*256, KVD,
                   bv + c*256, DM/32, (const float*)0, (const float*)0, 0);
    }
}

__global__ __launch_bounds__(256) void k_proj_o(
    const __half* __restrict__ X, const __half* __restrict__ Wt,
    float* __restrict__ C)
{
    tc_wide<1>(X + (size_t)blockIdx.y*128*DM, DM,
               Wt + (size_t)blockIdx.x*256*DM, DM,
               C + (size_t)blockIdx.y*128*DM + blockIdx.x*256, DM,
               (const float*)0, DM/32, (const float*)0, (const float*)0, 0);
}

// ======== scores: S fp16 + partials; upper tiles: zero-fill + V transpose ===
__global__ __launch_bounds__(256) void k_scores2(
    const __half* __restrict__ q, const __half* __restrict__ k,
    __half* __restrict__ sh, float* __restrict__ pm, float* __restrict__ pl,
    float* __restrict__ attn, const __half* __restrict__ vh,
    __half* __restrict__ vt, float scale)
{
    const int bx = blockIdx.x, by = blockIdx.y;
    const int bh = blockIdx.z, b = bh >> 4, h = bh & 15, hk = h >> 2;

    if (bx > by) {   // strictly-upper tile: zero-fill attn; some also move V
        float* base = attn + ((size_t)bh*SEQ + by*128)*SEQ + bx*128;
        const float4 z = make_float4(0.f, 0.f, 0.f, 0.f);
        for (int f = threadIdx.x; f < 128*32; f += 256) {
            const int r = f >> 5, c4 = f & 31;
            *(float4*)(base + (size_t)r*SEQ + c4*4) = z;
        }
        const int uid = bh*120 + (15*by - by*(by-1)/2) + (bx - by - 1);
        if (uid < 2048) {      // V transpose: 32x32 tile per CTA
            __shared__ __half vtile[32][33];
            const int zz = uid >> 8, rem = uid & 255;
            const int bb = zz >> 2, hk2 = zz & 3;
            const int c0 = (rem & 3) * 32;   // d
            const int r0 = (rem >> 2) * 32;  // s
            const int tx2 = threadIdx.x & 31, ty2 = threadIdx.x >> 5;
            #pragma unroll
            for (int i = 0; i < 32; i += 8)
                vtile[ty2 + i][tx2] =
                    vh[((size_t)bb*SEQ + r0 + ty2 + i)*KVD + hk2*HD + c0 + tx2];
            __syncthreads();
            #pragma unroll
            for (int i = 0; i < 32; i += 8)
                vt[((size_t)(bb*HKV + hk2)*HD + c0 + ty2 + i)*SEQ + r0 + tx2] =
                    vtile[tx2][ty2 + i];
        }
        return;
    }

    __shared__ __half As[2][128*40];
    __shared__ __half Bs[2][128*40];
    __shared__ float sm_m[4][128];
    __shared__ float sm_l[4][128];
    const int t = threadIdx.x, lane = t & 31, w = t >> 5;
    const int wm = w >> 2, wn = w & 3, gid = lane >> 2, tg = lane & 3;
    const int row = t >> 1, ch = (t & 1) * 16;

    float acc[4][4][4];
    ACC_INIT(acc)

    const __half* Ag = q + ((size_t)b*SEQ + by*128 + row) * DM  + h*HD  + ch;
    const __half* Bg = k + ((size_t)b*SEQ + bx*128 + row) * KVD + hk*HD + ch;
    uint32_t sa[2], sb[2];
    sa[0] = smem_u32(&As[0][row*40 + ch]);
    sa[1] = smem_u32(&As[1][row*40 + ch]);
    sb[0] = smem_u32(&Bs[0][row*40 + ch]);
    sb[1] = smem_u32(&Bs[1][row*40 + ch]);
    uint32_t aAddr[2], bAddr[2];
    #pragma unroll
    for (int s = 0; s < 2; ++s) {
        aAddr[s] = smem_u32(&As[s][0]) +
            (((wm*64 + (lane & 15)) * 40 + ((lane >> 4) << 3)) << 1);
        bAddr[s] = smem_u32(&Bs[s][0]) +
            (((wn*32 + (lane & 7)) * 40 + (((lane >> 3) & 1) << 3)) << 1);
    }

    cp16(sa[0], Ag);      cp16(sa[0] + 16, Ag + 8);
    cp16(sb[0], Bg);      cp16(sb[0] + 16, Bg + 8);
    CP_COMMIT();

    for (int it = 0; it < HD/32; ++it) {
        const int cur = it & 1;
        CP_WAIT0();
        __syncthreads();
        if (it + 1 < HD/32) {
            const int nxt = cur ^ 1;
            const __half* a = Ag + (size_t)(it + 1) * 32;
            const __half* b2 = Bg + (size_t)(it + 1) * 32;
            cp16(sa[nxt], a);  cp16(sa[nxt] + 16, a + 8);
            cp16(sb[nxt], b2); cp16(sb[nxt] + 16, b2 + 8);
            CP_COMMIT();
        }
        #pragma unroll
        for (int c = 0; c < 2; ++c) {
            uint32_t af[4][4], bf[4][2];
            #pragma unroll
            for (int mt = 0; mt < 4; ++mt)
                ldsm_x4(af[mt], aAddr[cur] + mt * 1280 + c * 32);
            #pragma unroll
            for (int nt = 0; nt < 4; ++nt)
                ldsm_x2(bf[nt], bAddr[cur] + nt * 640 + c * 32);
            #pragma unroll
            for (int mt = 0; mt < 4; ++mt)
                #pragma unroll
                for (int nt = 0; nt < 4; ++nt)
                    mma_f16(acc[mt][nt], af[mt], bf[nt]);
        }
    }

    const bool diag = (bx == by);
    __half* tile = sh + (((size_t)bh*NTILE + by)*NTILE + bx) * (128*128);

    #pragma unroll
    for (int mt = 0; mt < 4; ++mt) {
        #pragma unroll
        for (int hv = 0; hv < 2; ++hv) {
            const int r = wm*64 + mt*16 + gid + hv*8;
            float vals[8];
            #pragma unroll
            for (int nt = 0; nt < 4; ++nt) {
                vals[nt*2]   = acc[mt][nt][hv*2]   * scale;
                vals[nt*2+1] = acc[mt][nt][hv*2+1] * scale;
                const int cn = wn*32 + nt*8 + 2*tg;
                *(uint32_t*)(tile + (size_t)r*128 + cn) =
                    pack2(vals[nt*2], vals[nt*2+1]);
            }
            if (diag) {
                #pragma unroll
                for (int nt = 0; nt < 4; ++nt) {
                    const int cn = wn*32 + nt*8 + 2*tg;
                    if (cn     > r) vals[nt*2]   = -1e30f;
                    if (cn + 1 > r) vals[nt*2+1] = -1e30f;
                }
            }
            float m = -1e30f;
            #pragma unroll
            for (int i = 0; i < 8; ++i) m = fmaxf(m, vals[i]);
            m = fmaxf(m, __shfl_xor_sync(0xFFFFFFFFu, m, 1));
            m = fmaxf(m, __shfl_xor_sync(0xFFFFFFFFu, m, 2));
            float l = 0.f;
            #pragma unroll
            for (int i = 0; i < 8; ++i)
                if (vals[i] > -1e29f) l += __expf(vals[i] - m);
            l += __shfl_xor_sync(0xFFFFFFFFu, l, 1);
            l += __shfl_xor_sync(0xFFFFFFFFu, l, 2);
            if (tg == 0) { sm_m[wn][r] = m; sm_l[wn][r] = l; }
        }
    }
    __syncthreads();
    if (t < 128) {
        float M = -1e30f;
        #pragma unroll
        for (int w2 = 0; w2 < 4; ++w2) M = fmaxf(M, sm_m[w2][t]);
        float L = 0.f;
        #pragma unroll
        for (int w2 = 0; w2 < 4; ++w2)
            if (sm_m[w2][t] > -1e29f) L += sm_l[w2][t] * __expf(sm_m[w2][t] - M);
        const size_t ridx = ((size_t)bh*SEQ + by*128 + t) * NTILE + bx;
        pm[ridx] = M; pl[ridx] = L;
    }
}

// ======== fused reduce + normalize + P write + P@V ==========================
__global__ __launch_bounds__(256) void k_pv(
    const __half* __restrict__ sh, const float* __restrict__ pm,
    const float* __restrict__ pl, const __half* __restrict__ vt,
    float* __restrict__ attn, __half* __restrict__ ao)
{
    const int by = NTILE - 1 - blockIdx.x;       // big tiles first
    const int bh = blockIdx.y;
    const int b = bh >> 4, h = bh & 15, hk = h >> 2;
    const int i0 = by * 128;

    __shared__ __half As[128*40];
    __shared__ __half Bs[128*40];
    __shared__ float sM[128], sL[128];
    const int t = threadIdx.x, lane = t & 31, w = t >> 5;
    const int wm = w >> 2, wn = w & 3, gid = lane >> 2, tg = lane & 3;
    const int row = t >> 1, ch = (t & 1) * 16;

    if (t < 128) {
        const float* pmr = pm + ((size_t)bh*SEQ + i0 + t) * NTILE;
        const float* plr = pl + ((size_t)bh*SEQ + i0 + t) * NTILE;
        float M = -1e30f;
        for (int t2 = 0; t2 <= by; ++t2) M = fmaxf(M, pmr[t2]);
        float L = 0.f;
        for (int t2 = 0; t2 <= by; ++t2)
            if (pmr[t2] > -1e29f) L += plr[t2] * __expf(pmr[t2] - M);
        sM[t] = M; sL[t] = 1.0f / L;
    }

    float acc[4][4][4];
    ACC_INIT(acc)

    const __half* shb = sh + ((size_t)bh*NTILE + by)*NTILE*(128*128);
    const __half* vtp = vt + (size_t)(b*HKV + hk)*HD*SEQ + (size_t)row*SEQ + ch;
    float* arow = attn + ((size_t)bh*SEQ + i0 + row)*SEQ;

    const uint32_t aAddr = smem_u32(As) +
        (((wm*64 + (lane & 15)) * 40 + ((lane >> 4) << 3)) << 1);
    const uint32_t bAddr = smem_u32(Bs) +
        (((wn*32 + (lane & 7)) * 40 + (((lane >> 3) & 1) << 3)) << 1);

    const int njc = (by + 1) * 4;

    auto sptr = [&](int jc) -> const __half* {
        const int tj = jc >> 2, jin = (jc & 3) * 32;
        return shb + (size_t)tj*(128*128) + (size_t)row*128 + jin + ch;
    };

    uint4 sv0, sv1, vv0, vv1;
    {
        const __half* sp = sptr(0);
        sv0 = *(const uint4*)sp;  sv1 = *(const uint4*)(sp + 8);
        vv0 = *(const uint4*)vtp; vv1 = *(const uint4*)(vtp + 8);
    }
    __syncthreads();
    const float Mrow = sM[row], invL = sL[row];

    for (int jc = 0; jc < njc; ++jc) {
        const int tj = jc >> 2, jin = (jc & 3) * 32;

        float p[16];
        {
            const __half2* h2 = (const __half2*)&sv0;
            #pragma unroll
            for (int g = 0; g < 4; ++g) {
                float2 f = __half22float2(h2[g]);
                p[g*2]   = __expf(f.x - Mrow) * invL;
                p[g*2+1] = __expf(f.y - Mrow) * invL;
            }
            const __half2* h3 = (const __half2*)&sv1;
            #pragma unroll
            for (int g = 0; g < 4; ++g) {
                float2 f = __half22float2(h3[g]);
                p[8+g*2]   = __expf(f.x - Mrow) * invL;
                p[8+g*2+1] = __expf(f.y - Mrow) * invL;
            }
        }
        if (tj == by) {
            #pragma unroll
            for (int kk = 0; kk < 16; ++kk)
                if (jin + ch + kk > row) p[kk] = 0.f;
        }
        float* ap = arow + tj*128 + jin + ch;
        *(float4*)(ap)      = make_float4(p[0],  p[1],  p[2],  p[3]);
        *(float4*)(ap + 4)  = make_float4(p[4],  p[5],  p[6],  p[7]);
        *(float4*)(ap + 8)  = make_float4(p[8],  p[9],  p[10], p[11]);
        *(float4*)(ap + 12) = make_float4(p[12], p[13], p[14], p[15]);

        uint4* aw = (uint4*)&As[row*40 + ch];
        aw[0] = make_uint4(pack2(p[0],p[1]),  pack2(p[2],p[3]),
                           pack2(p[4],p[5]),  pack2(p[6],p[7]));
        aw[1] = make_uint4(pack2(p[8],p[9]),  pack2(p[10],p[11]),
                           pack2(p[12],p[13]),pack2(p[14],p[15]));
        uint4* bw = (uint4*)&Bs[row*40 + ch];
        bw[0] = vv0;
        bw[1] = vv1;

        if (jc + 1 < njc) {
            const __half* sp = sptr(jc + 1);
            sv0 = *(const uint4*)sp;  sv1 = *(const uint4*)(sp + 8);
            const __half* vp = vtp + (jc + 1)*32;
            vv0 = *(const uint4*)vp;  vv1 = *(const uint4*)(vp + 8);
        }
        __syncthreads();

        #pragma unroll
        for (int c = 0; c < 2; ++c) {
            uint32_t af[4][4], bf[4][2];
            #pragma unroll
            for (int mt = 0; mt < 4; ++mt)
                ldsm_x4(af[mt], aAddr + mt * 1280 + c * 32);
            #pragma unroll
            for (int nt = 0; nt < 4; ++nt)
                ldsm_x2(bf[nt], bAddr + nt * 640 + c * 32);
            #pragma unroll
            for (int mt = 0; mt < 4; ++mt)
                #pragma unroll
                for (int nt = 0; nt < 4; ++nt)
                    mma_f16(acc[mt][nt], af[mt], bf[nt]);
        }
        __syncthreads();
    }

    #pragma unroll
    for (int mt = 0; mt < 4; ++mt) {
        const int r0 = wm*64 + mt*16 + gid;
        #pragma unroll
        for (int nt = 0; nt < 4; ++nt) {
            const int cn = wn*32 + nt*8 + 2*tg;
            __half* C = ao + ((size_t)b*SEQ + i0)*DM + h*HD;
            *(uint32_t*)(C + (size_t)r0*DM + cn) =
                pack2(acc[mt][nt][0], acc[mt][nt][1]);
            *(uint32_t*)(C + (size_t)(r0+8)*DM + cn) =
                pack2(acc[mt][nt][2], acc[mt][nt][3]);
        }
    }
}

// ======== fused conversions: x -> fp16, all weights -> fp16 transposed ======
__global__ __launch_bounds__(256) void k_cvt_all(
    const float* __restrict__ x,  __half* __restrict__ xh,
    const float* __restrict__ wq, __half* __restrict__ wqt,
    const float* __restrict__ wk, __half* __restrict__ wkt,
    const float* __restrict__ wv, __half* __restrict__ wvt,
    const float* __restrict__ wo, __half* __restrict__ wot)
{
    const int bid = blockIdx.x;
    if (bid < 8192) {     // x convert: 8192*256 float4 = MROWS*DM/4 exactly
        const int i = bid * 256 + threadIdx.x;
        float4 v = ((const float4*)x)[i];
        ((uint2*)xh)[i] = make_uint2(pack2(v.x, v.y), pack2(v.z, v.w));
        return;
    }
    int u = bid - 8192;
    const float* src; __half* dst; int N, r0, c0;
    if (u < 4096)      {            src = wq; dst = wqt; N = DM;
                         c0 = (u & 63) * 32; r0 = (u >> 6) * 32; }
    else if (u < 5120) { u -= 4096; src = wk; dst = wkt; N = KVD;
                         c0 = (u & 15) * 32; r0 = (u >> 4) * 32; }
    else if (u < 6144) { u -= 5120; src = wv; dst = wvt; N = KVD;
                         c0 = (u & 15) * 32; r0 = (u >> 4) * 32; }
    else               { u -= 6144; src = wo; dst = wot; N = DM;
                         c0 = (u & 63) * 32; r0 = (u >> 6) * 32; }
    __shared__ float tile[32][33];
    const int tx = threadIdx.x & 31, ty = threadIdx.x >> 5;
    #pragma unroll
    for (int i = 0; i < 32; i += 8)
        tile[ty + i][tx] = src[(size_t)(r0 + ty + i) * N + c0 + tx];
    __syncthreads();
    #pragma unroll
    for (int i = 0; i < 32; i += 8)
        dst[(size_t)(c0 + ty + i) * DM + r0 + tx] = __float2half(tile[tx][ty + i]);
}

// ---------------- launch ------------------------------------------------------
extern "C" void kernel_launch(void* const* d_in, const int* in_sizes, int n_in,
                              void* d_out, int out_size)
{
    const float* x  = (const float*)d_in[0];
    const float* fc = (const float*)d_in[1];
    const float* fs = (const float*)d_in[2];
    const float* wq = (const float*)d_in[3];
    const float* bq = (const float*)d_in[4];
    const float* wk = (const float*)d_in[5];
    const float* bk = (const float*)d_in[6];
    const float* wv = (const float*)d_in[7];
    const float* bv = (const float*)d_in[8];
    const float* wo = (const float*)d_in[9];

    float* outp = (float*)d_out;
    float* attn = outp + (size_t)BSZ * SEQ * DM;

    __half *xh, *qh, *kh, *vh, *vt, *aoh, *wqt, *wkt, *wvt, *wot, *sh;
    float *pm, *pl;
    cudaGetSymbolAddress((void**)&xh,  g_xh);
    cudaGetSymbolAddress((void**)&qh,  g_qh);
    cudaGetSymbolAddress((void**)&kh,  g_kh);
    cudaGetSymbolAddress((void**)&vh,  g_vh);
    cudaGetSymbolAddress((void**)&vt,  g_vt);
    cudaGetSymbolAddress((void**)&aoh, g_aoh);
    cudaGetSymbolAddress((void**)&wqt, g_wqt);
    cudaGetSymbolAddress((void**)&wkt, g_wkt);
    cudaGetSymbolAddress((void**)&wvt, g_wvt);
    cudaGetSymbolAddress((void**)&wot, g_wot);
    cudaGetSymbolAddress((void**)&sh,  g_sh);
    cudaGetSymbolAddress((void**)&pm,  g_pm);
    cudaGetSymbolAddress((void**)&pl,  g_pl);

    cudaFuncSetAttribute(k_qkv,   cudaFuncAttributeMaxDynamicSharedMemorySize, PROJ_SMEM);
    cudaFuncSetAttribute(k_proj_o,cudaFuncAttributeMaxDynamicSharedMemorySize, PROJ_SMEM);

    const float scale = 1.0f / sqrtf((float)DM);

    // single fused conversion launch (x + 4 weights)
    k_cvt_all<<<8192 + 10240, 256>>>(x, xh, wq, wqt, wk, wkt, wv, wvt, wo, wot);

    // fused QKV projection + RoPE (wide tiles)
    k_qkv<<<dim3(12, MROWS/128), 256, PROJ_SMEM>>>(xh, wqt, wkt, wvt, bq, bk, bv,
                                                   qh, kh, vh, fc, fs);

    // scores (+ upper zero-fill + V transpose in idle CTAs)
    k_scores2<<<dim3(NTILE, NTILE, NBH), 256>>>(qh, kh, sh, pm, pl, attn,
                                                vh, vt, scale);
    k_pv<<<dim3(NTILE, NBH), 256>>>(sh, pm, pl, vt, attn, aoh);

    k_proj_o<<<dim3(DM/256, MROWS/128), 256, PROJ_SMEM>>>(aoh, wot, outp);
}